// round 1
// baseline (speedup 1.0000x reference)
#include <cuda_runtime.h>
#include <math.h>

// Problem shape (from reference setup_inputs): phi (64,256), X (256,N), Y (64,N)
constexpr int M    = 64;    // rows of phi / Y
constexpr int NROW = 256;   // rows of X = cols of phi
constexpr int TPB  = 256;   // one thread per column
constexpr int MH   = M / 2; // packed f32x2 count for the 64-dim
constexpr int PHI_STRIDE = MH + 1; // u64 per shared row (pad -> conflict-free)
constexpr int SMEM_BYTES = NROW * PHI_STRIDE * 8; // 256*33*8 = 67584

// ---- packed f32x2 helpers (Blackwell FFMA2: only reachable via PTX) ----
__device__ __forceinline__ unsigned long long fma2(unsigned long long a,
                                                   unsigned long long b,
                                                   unsigned long long c) {
    unsigned long long d;
    asm("fma.rn.f32x2 %0, %1, %2, %3;" : "=l"(d) : "l"(a), "l"(b), "l"(c));
    return d;
}
__device__ __forceinline__ unsigned long long add2(unsigned long long a,
                                                   unsigned long long b) {
    unsigned long long d;
    asm("add.rn.f32x2 %0, %1, %2;" : "=l"(d) : "l"(a), "l"(b));
    return d;
}
__device__ __forceinline__ unsigned long long pack2(float lo, float hi) {
    unsigned long long d;
    asm("mov.b64 %0, {%1, %2};" : "=l"(d) : "f"(lo), "f"(hi));
    return d;
}
__device__ __forceinline__ void unpack2(unsigned long long v, float& lo, float& hi) {
    asm("mov.b64 {%0, %1}, %2;" : "=f"(lo), "=f"(hi) : "l"(v));
}

extern __shared__ unsigned long long phi2_s[]; // [NROW][PHI_STRIDE]

__global__ __launch_bounds__(TPB)
void ista_update_kernel(const float* __restrict__ phi,
                        const float* __restrict__ X,
                        const float* __restrict__ Y,
                        const float* __restrict__ step,
                        const int*   __restrict__ idxp,
                        float*       __restrict__ outX,
                        int K)
{
    const int j = blockIdx.x * TPB + threadIdx.x;
    const int k = *idxp + 1; // uniform device-side scalar (graph-safe)

    // Cooperative load of phi, transposed + f32x2-packed:
    // phi2_s[n][ii] = (phi[2ii][n], phi[2ii+1][n]).
    // Global reads coalesced across t (= n); shared writes 2-way at worst (padded rows).
    {
        const int t = threadIdx.x; // n index, 0..255
        #pragma unroll
        for (int ii = 0; ii < MH; ++ii) {
            float lo = phi[(2 * ii)     * NROW + t];
            float hi = phi[(2 * ii + 1) * NROW + t];
            phi2_s[t * PHI_STRIDE + ii] = pack2(lo, hi);
        }
    }
    __syncthreads();

    if (j >= K) return;

    if (j >= k) {
        // Tail columns: passthrough copy (coalesced 128B/warp).
        #pragma unroll 4
        for (int n = 0; n < NROW; ++n)
            outX[(size_t)n * K + j] = X[(size_t)n * K + j];
        return;
    }

    const float s = *step;

    // r = Y[:, j]   (32 packed registers)
    unsigned long long r2[MH];
    #pragma unroll
    for (int ii = 0; ii < MH; ++ii)
        r2[ii] = pack2(Y[(size_t)(2 * ii) * K + j],
                       Y[(size_t)(2 * ii + 1) * K + j]);

    // Phase 1: r -= phi @ x   (independent chains across ii)
    for (int n = 0; n < NROW; ++n) {
        float xv = X[(size_t)n * K + j];
        unsigned long long nx2 = pack2(-xv, -xv);
        const unsigned long long* prow = &phi2_s[n * PHI_STRIDE];
        #pragma unroll
        for (int ii = 0; ii < MH; ++ii)
            r2[ii] = fma2(prow[ii], nx2, r2[ii]);
    }

    // Phase 2: u[n] = x[n] + s * <phi[:,n], r>, threshold, store.
    // 4 interleaved packed accumulators break the serial FMA chain.
    for (int n = 0; n < NROW; ++n) {
        const unsigned long long* prow = &phi2_s[n * PHI_STRIDE];
        unsigned long long a0 = 0ull, a1 = 0ull, a2 = 0ull, a3 = 0ull;
        #pragma unroll
        for (int ii = 0; ii < MH; ii += 4) {
            a0 = fma2(prow[ii + 0], r2[ii + 0], a0);
            a1 = fma2(prow[ii + 1], r2[ii + 1], a1);
            a2 = fma2(prow[ii + 2], r2[ii + 2], a2);
            a3 = fma2(prow[ii + 3], r2[ii + 3], a3);
        }
        unsigned long long a = add2(add2(a0, a1), add2(a2, a3));
        float lo, hi;
        unpack2(a, lo, hi);
        float u = X[(size_t)n * K + j] + s * (lo + hi);
        u = (fabsf(u) > 0.1f) ? u : 0.0f;
        outX[(size_t)n * K + j] = u;
    }
}

extern "C" void kernel_launch(void* const* d_in, const int* in_sizes, int n_in,
                              void* d_out, int out_size)
{
    const float* phi  = (const float*)d_in[0];
    const float* X    = (const float*)d_in[1];
    const float* Y    = (const float*)d_in[2];
    const float* step = (const float*)d_in[3];
    const int*   idx  = (const int*)d_in[4]; // low word correct for i32 or LE i64

    const int phiN = in_sizes[0];        // 64*256 = 16384
    const int XN   = in_sizes[1];        // 256*K
    const int K    = XN / NROW;          // 131072

    float* outX = (float*)d_out;
    if (out_size == phiN + XN) {
        // Output is (phi, X) concatenated: phi passes through unchanged.
        cudaMemcpyAsync(d_out, phi, (size_t)phiN * sizeof(float),
                        cudaMemcpyDeviceToDevice, 0);
        outX = (float*)d_out + phiN;
    }

    cudaFuncSetAttribute(ista_update_kernel,
                         cudaFuncAttributeMaxDynamicSharedMemorySize, SMEM_BYTES);

    const int grid = (K + TPB - 1) / TPB;
    ista_update_kernel<<<grid, TPB, SMEM_BYTES>>>(phi, X, Y, step, idx, outX, K);
}

// round 2
// speedup vs baseline: 1.0218x; 1.0218x over previous
#include <cuda_runtime.h>
#include <math.h>

// Problem shape (from reference setup_inputs): phi (64,256), X (256,N), Y (64,N)
constexpr int M    = 64;    // rows of phi / Y
constexpr int NROW = 256;   // rows of X = cols of phi
constexpr int TPB  = 256;   // one thread per column
constexpr int MH   = M / 2; // packed f32x2 count for the 64-dim
constexpr int PHI_STRIDE = MH + 1; // u64 per shared row (pad -> conflict-free)
constexpr int SMEM_BYTES = NROW * PHI_STRIDE * 8; // 256*33*8 = 67584

// ---- packed f32x2 helpers (Blackwell FFMA2: only reachable via PTX) ----
__device__ __forceinline__ unsigned long long fma2(unsigned long long a,
                                                   unsigned long long b,
                                                   unsigned long long c) {
    unsigned long long d;
    asm("fma.rn.f32x2 %0, %1, %2, %3;" : "=l"(d) : "l"(a), "l"(b), "l"(c));
    return d;
}
__device__ __forceinline__ unsigned long long add2(unsigned long long a,
                                                   unsigned long long b) {
    unsigned long long d;
    asm("add.rn.f32x2 %0, %1, %2;" : "=l"(d) : "l"(a), "l"(b));
    return d;
}
__device__ __forceinline__ unsigned long long pack2(float lo, float hi) {
    unsigned long long d;
    asm("mov.b64 %0, {%1, %2};" : "=l"(d) : "f"(lo), "f"(hi));
    return d;
}
__device__ __forceinline__ void unpack2(unsigned long long v, float& lo, float& hi) {
    asm("mov.b64 {%0, %1}, %2;" : "=f"(lo), "=f"(hi) : "l"(v));
}

extern __shared__ unsigned long long phi2_s[]; // [NROW][PHI_STRIDE]

__global__ __launch_bounds__(TPB)
void ista_update_kernel(const float* __restrict__ phi,
                        const float* __restrict__ X,
                        const float* __restrict__ Y,
                        const float* __restrict__ step,
                        const int*   __restrict__ idxp,
                        float*       __restrict__ outX,
                        int K)
{
    const int j = blockIdx.x * TPB + threadIdx.x;
    const int k = *idxp + 1; // uniform device-side scalar (graph-safe)

    // Cooperative load of phi, transposed + f32x2-packed:
    // phi2_s[n][ii] = (phi[2ii][n], phi[2ii+1][n]).
    // Global reads coalesced across t (= n); shared writes 2-way at worst (padded rows).
    {
        const int t = threadIdx.x; // n index, 0..255
        #pragma unroll
        for (int ii = 0; ii < MH; ++ii) {
            float lo = phi[(2 * ii)     * NROW + t];
            float hi = phi[(2 * ii + 1) * NROW + t];
            phi2_s[t * PHI_STRIDE + ii] = pack2(lo, hi);
        }
    }
    __syncthreads();

    if (j >= K) return;

    if (j >= k) {
        // Tail columns: passthrough copy (coalesced 128B/warp).
        #pragma unroll 4
        for (int n = 0; n < NROW; ++n)
            outX[(size_t)n * K + j] = X[(size_t)n * K + j];
        return;
    }

    const float s = *step;

    // r = Y[:, j]   (32 packed registers)
    unsigned long long r2[MH];
    #pragma unroll
    for (int ii = 0; ii < MH; ++ii)
        r2[ii] = pack2(Y[(size_t)(2 * ii) * K + j],
                       Y[(size_t)(2 * ii + 1) * K + j]);

    // Phase 1: r -= phi @ x   (independent chains across ii)
    for (int n = 0; n < NROW; ++n) {
        float xv = X[(size_t)n * K + j];
        unsigned long long nx2 = pack2(-xv, -xv);
        const unsigned long long* prow = &phi2_s[n * PHI_STRIDE];
        #pragma unroll
        for (int ii = 0; ii < MH; ++ii)
            r2[ii] = fma2(prow[ii], nx2, r2[ii]);
    }

    // Phase 2: u[n] = x[n] + s * <phi[:,n], r>, threshold, store.
    // 4 interleaved packed accumulators break the serial FMA chain.
    for (int n = 0; n < NROW; ++n) {
        const unsigned long long* prow = &phi2_s[n * PHI_STRIDE];
        unsigned long long a0 = 0ull, a1 = 0ull, a2 = 0ull, a3 = 0ull;
        #pragma unroll
        for (int ii = 0; ii < MH; ii += 4) {
            a0 = fma2(prow[ii + 0], r2[ii + 0], a0);
            a1 = fma2(prow[ii + 1], r2[ii + 1], a1);
            a2 = fma2(prow[ii + 2], r2[ii + 2], a2);
            a3 = fma2(prow[ii + 3], r2[ii + 3], a3);
        }
        unsigned long long a = add2(add2(a0, a1), add2(a2, a3));
        float lo, hi;
        unpack2(a, lo, hi);
        float u = X[(size_t)n * K + j] + s * (lo + hi);
        u = (fabsf(u) > 0.1f) ? u : 0.0f;
        outX[(size_t)n * K + j] = u;
    }
}

extern "C" void kernel_launch(void* const* d_in, const int* in_sizes, int n_in,
                              void* d_out, int out_size)
{
    const float* phi  = (const float*)d_in[0];
    const float* X    = (const float*)d_in[1];
    const float* Y    = (const float*)d_in[2];
    const float* step = (const float*)d_in[3];
    const int*   idx  = (const int*)d_in[4]; // low word correct for i32 or LE i64

    const int phiN = in_sizes[0];        // 64*256 = 16384
    const int XN   = in_sizes[1];        // 256*K
    const int K    = XN / NROW;          // 131072

    float* outX = (float*)d_out;
    if (out_size == phiN + XN) {
        // Output is (phi, X) concatenated: phi passes through unchanged.
        cudaMemcpyAsync(d_out, phi, (size_t)phiN * sizeof(float),
                        cudaMemcpyDeviceToDevice, 0);
        outX = (float*)d_out + phiN;
    }

    cudaFuncSetAttribute(ista_update_kernel,
                         cudaFuncAttributeMaxDynamicSharedMemorySize, SMEM_BYTES);

    const int grid = (K + TPB - 1) / TPB;
    ista_update_kernel<<<grid, TPB, SMEM_BYTES>>>(phi, X, Y, step, idx, outX, K);
}

// round 3
// speedup vs baseline: 2.0502x; 2.0064x over previous
#include <cuda_runtime.h>
#include <math.h>

// phi (64,256), X (256,K), Y (64,K), K=131072, k=idx+1 active columns.
constexpr int M    = 64;
constexpr int NROW = 256;
constexpr int TPB  = 256;
constexpr int MH   = M / 2;        // 32 packed f32x2 per column residual
constexpr int MQ   = MH / 2;       // 16 ulonglong2 per phi row
constexpr int SMEM_BYTES = NROW * MQ * 16;  // 256*16*16 = 65536

// ---- packed f32x2 helpers (FFMA2 only reachable via PTX) ----
__device__ __forceinline__ unsigned long long fma2(unsigned long long a,
                                                   unsigned long long b,
                                                   unsigned long long c) {
    unsigned long long d;
    asm("fma.rn.f32x2 %0, %1, %2, %3;" : "=l"(d) : "l"(a), "l"(b), "l"(c));
    return d;
}
__device__ __forceinline__ unsigned long long add2(unsigned long long a,
                                                   unsigned long long b) {
    unsigned long long d;
    asm("add.rn.f32x2 %0, %1, %2;" : "=l"(d) : "l"(a), "l"(b));
    return d;
}
__device__ __forceinline__ unsigned long long pack2(float lo, float hi) {
    unsigned long long d;
    asm("mov.b64 %0, {%1, %2};" : "=l"(d) : "f"(lo), "f"(hi));
    return d;
}
__device__ __forceinline__ void unpack2(unsigned long long v, float& lo, float& hi) {
    asm("mov.b64 {%0, %1}, %2;" : "=f"(lo), "=f"(hi) : "l"(v));
}

extern __shared__ ulonglong2 phi2_s[]; // [NROW][MQ], 256B/row, 16B aligned

__global__ __launch_bounds__(TPB, 2)
void ista_update_kernel(const float* __restrict__ phi,
                        const float* __restrict__ X,
                        const float* __restrict__ Y,
                        const float* __restrict__ step,
                        const int*   __restrict__ idxp,
                        float*       __restrict__ outX,
                        int K)
{
    const int j = blockIdx.x * TPB + threadIdx.x;
    const int k = *idxp + 1;

    const bool block_all_tail = (blockIdx.x * TPB >= k);

    if (!block_all_tail) {
        // Cooperative fill: phi2_s[n][ii] = (phi[2ii][n], phi[2ii+1][n]) packed pairs.
        const int t = threadIdx.x;
        #pragma unroll
        for (int ii = 0; ii < MQ; ++ii) {
            ulonglong2 v;
            v.x = pack2(phi[(4 * ii + 0) * NROW + t], phi[(4 * ii + 1) * NROW + t]);
            v.y = pack2(phi[(4 * ii + 2) * NROW + t], phi[(4 * ii + 3) * NROW + t]);
            phi2_s[t * MQ + ii] = v;
        }
        __syncthreads();
    }

    if (j >= K) return;

    if (j >= k) {
        // Passthrough columns: coalesced strided copy.
        #pragma unroll 8
        for (int n = 0; n < NROW; ++n)
            outX[(size_t)n * K + j] = X[(size_t)n * K + j];
        return;
    }

    const float s = *step;

    // r = Y[:, j] (32 packed regs); 64 independent LDGs -> good MLP.
    unsigned long long r2[MH];
    #pragma unroll
    for (int ii = 0; ii < MH; ++ii)
        r2[ii] = pack2(Y[(size_t)(2 * ii)     * K + j],
                       Y[(size_t)(2 * ii + 1) * K + j]);

    // ---------- Phase 1: r -= phi @ x, X prefetched 4 iterations ahead ----------
    {
        float xb[4];
        #pragma unroll
        for (int p = 0; p < 4; ++p) xb[p] = X[(size_t)p * K + j];

        #pragma unroll 1
        for (int n = 0; n < NROW; n += 4) {
            float xc[4];
            #pragma unroll
            for (int p = 0; p < 4; ++p) xc[p] = xb[p];
            // prefetch next group (clamped; redundant loads on last iter are harmless)
            #pragma unroll
            for (int p = 0; p < 4; ++p) {
                int np = n + 4 + p;
                np = (np < NROW) ? np : 0;
                xb[p] = X[(size_t)np * K + j];
            }
            #pragma unroll
            for (int p = 0; p < 4; ++p) {
                const unsigned long long nx2 = pack2(-xc[p], -xc[p]);
                const ulonglong2* prow = &phi2_s[(n + p) * MQ];
                #pragma unroll
                for (int ii = 0; ii < MQ; ++ii) {
                    ulonglong2 ph = prow[ii];
                    r2[2 * ii]     = fma2(ph.x, nx2, r2[2 * ii]);
                    r2[2 * ii + 1] = fma2(ph.y, nx2, r2[2 * ii + 1]);
                }
            }
        }
    }

    // ---------- Phase 2: u[n] = x[n] + s*<phi[:,n], r>, 2 n's interleaved ----------
    {
        float xb[4];
        #pragma unroll
        for (int p = 0; p < 4; ++p) xb[p] = X[(size_t)p * K + j];

        #pragma unroll 1
        for (int n = 0; n < NROW; n += 4) {
            float xc[4];
            #pragma unroll
            for (int p = 0; p < 4; ++p) xc[p] = xb[p];
            #pragma unroll
            for (int p = 0; p < 4; ++p) {
                int np = n + 4 + p;
                np = (np < NROW) ? np : 0;
                xb[p] = X[(size_t)np * K + j];
            }
            // two pairs of columns, each pair = 4 independent FMA chains
            #pragma unroll
            for (int q = 0; q < 2; ++q) {
                const ulonglong2* pa = &phi2_s[(n + 2 * q)     * MQ];
                const ulonglong2* pb = &phi2_s[(n + 2 * q + 1) * MQ];
                unsigned long long a0 = 0ull, a1 = 0ull, b0 = 0ull, b1 = 0ull;
                #pragma unroll
                for (int ii = 0; ii < MQ; ++ii) {
                    ulonglong2 pha = pa[ii];
                    ulonglong2 phb = pb[ii];
                    a0 = fma2(pha.x, r2[2 * ii],     a0);
                    a1 = fma2(pha.y, r2[2 * ii + 1], a1);
                    b0 = fma2(phb.x, r2[2 * ii],     b0);
                    b1 = fma2(phb.y, r2[2 * ii + 1], b1);
                }
                float alo, ahi, blo, bhi;
                unpack2(add2(a0, a1), alo, ahi);
                unpack2(add2(b0, b1), blo, bhi);
                float ua = fmaf(s, alo + ahi, xc[2 * q]);
                float ub = fmaf(s, blo + bhi, xc[2 * q + 1]);
                ua = (fabsf(ua) > 0.1f) ? ua : 0.0f;
                ub = (fabsf(ub) > 0.1f) ? ub : 0.0f;
                outX[(size_t)(n + 2 * q)     * K + j] = ua;
                outX[(size_t)(n + 2 * q + 1) * K + j] = ub;
            }
        }
    }
}

extern "C" void kernel_launch(void* const* d_in, const int* in_sizes, int n_in,
                              void* d_out, int out_size)
{
    const float* phi  = (const float*)d_in[0];
    const float* X    = (const float*)d_in[1];
    const float* Y    = (const float*)d_in[2];
    const float* step = (const float*)d_in[3];
    const int*   idx  = (const int*)d_in[4];

    const int phiN = in_sizes[0];
    const int XN   = in_sizes[1];
    const int K    = XN / NROW;

    float* outX = (float*)d_out;
    if (out_size == phiN + XN) {
        cudaMemcpyAsync(d_out, phi, (size_t)phiN * sizeof(float),
                        cudaMemcpyDeviceToDevice, 0);
        outX = (float*)d_out + phiN;
    }

    cudaFuncSetAttribute(ista_update_kernel,
                         cudaFuncAttributeMaxDynamicSharedMemorySize, SMEM_BYTES);

    const int grid = (K + TPB - 1) / TPB;
    ista_update_kernel<<<grid, TPB, SMEM_BYTES>>>(phi, X, Y, step, idx, outX, K);
}

// round 4
// speedup vs baseline: 2.0720x; 1.0106x over previous
#include <cuda_runtime.h>
#include <math.h>

// phi (64,256), X (256,K), Y (64,K); k = idx+1 active columns.
constexpr int M    = 64;
constexpr int NROW = 256;
constexpr int TPB  = 128;           // 2 columns per thread -> 256 cols per CTA
constexpr int CPB  = 256;           // columns per CTA
constexpr int MH   = M / 2;         // 32 packed f32x2 per column
constexpr int MQ   = MH / 2;        // 16 ulonglong2 per phi row
constexpr int SMEM_BYTES = NROW * MQ * 16; // 65536

__device__ __forceinline__ unsigned long long fma2(unsigned long long a,
                                                   unsigned long long b,
                                                   unsigned long long c) {
    unsigned long long d;
    asm("fma.rn.f32x2 %0, %1, %2, %3;" : "=l"(d) : "l"(a), "l"(b), "l"(c));
    return d;
}
__device__ __forceinline__ unsigned long long add2(unsigned long long a,
                                                   unsigned long long b) {
    unsigned long long d;
    asm("add.rn.f32x2 %0, %1, %2;" : "=l"(d) : "l"(a), "l"(b));
    return d;
}
__device__ __forceinline__ unsigned long long pack2(float lo, float hi) {
    unsigned long long d;
    asm("mov.b64 %0, {%1, %2};" : "=l"(d) : "f"(lo), "f"(hi));
    return d;
}
__device__ __forceinline__ void unpack2(unsigned long long v, float& lo, float& hi) {
    asm("mov.b64 {%0, %1}, %2;" : "=f"(lo), "=f"(hi) : "l"(v));
}

extern __shared__ ulonglong2 phi2_s[]; // [NROW][MQ]

__global__ __launch_bounds__(TPB, 2)
void ista_update_kernel(const float* __restrict__ phi,
                        const float* __restrict__ X,
                        const float* __restrict__ Y,
                        const float* __restrict__ step,
                        const int*   __restrict__ idxp,
                        float*       __restrict__ outX,
                        int K)
{
    const int t    = threadIdx.x;
    const int base = blockIdx.x * CPB;
    const int j0   = base + t;
    const int j1   = j0 + TPB;
    const int k    = *idxp + 1;

    if (base >= k) {
        // Pure passthrough block: coalesced copy of both columns.
        if (j0 < K) {
            #pragma unroll 8
            for (int n = 0; n < NROW; ++n)
                outX[(size_t)n * K + j0] = X[(size_t)n * K + j0];
        }
        if (j1 < K) {
            #pragma unroll 8
            for (int n = 0; n < NROW; ++n)
                outX[(size_t)n * K + j1] = X[(size_t)n * K + j1];
        }
        return;
    }

    // Cooperative phi fill: phi2_s[n][ii] = packed pairs of phi[:, n].
    #pragma unroll
    for (int rr = 0; rr < NROW / TPB; ++rr) {
        const int n = t + rr * TPB;
        #pragma unroll
        for (int ii = 0; ii < MQ; ++ii) {
            ulonglong2 v;
            v.x = pack2(phi[(4 * ii + 0) * NROW + n], phi[(4 * ii + 1) * NROW + n]);
            v.y = pack2(phi[(4 * ii + 2) * NROW + n], phi[(4 * ii + 3) * NROW + n]);
            phi2_s[n * MQ + ii] = v;
        }
    }
    __syncthreads();

    const float s = *step;
    const bool act0 = (j0 < k);
    const bool act1 = (j1 < k);

    // ---------------- Phase 1: s2 = phi @ x  (both columns) ----------------
    unsigned long long s2a[MH], s2b[MH];
    #pragma unroll
    for (int ii = 0; ii < MH; ++ii) { s2a[ii] = 0ull; s2b[ii] = 0ull; }

    {
        float xb0[4], xb1[4];
        #pragma unroll
        for (int p = 0; p < 4; ++p) {
            xb0[p] = X[(size_t)p * K + j0];
            xb1[p] = X[(size_t)p * K + j1];
        }

        #pragma unroll 1
        for (int n = 0; n < NROW; n += 4) {
            float xc0[4], xc1[4];
            #pragma unroll
            for (int p = 0; p < 4; ++p) { xc0[p] = xb0[p]; xc1[p] = xb1[p]; }
            #pragma unroll
            for (int p = 0; p < 4; ++p) {
                int np = n + 4 + p; np = (np < NROW) ? np : 0;
                xb0[p] = X[(size_t)np * K + j0];
                xb1[p] = X[(size_t)np * K + j1];
            }
            #pragma unroll
            for (int p = 0; p < 4; ++p) {
                const unsigned long long x0_2 = pack2(xc0[p], xc0[p]);
                const unsigned long long x1_2 = pack2(xc1[p], xc1[p]);
                const ulonglong2* prow = &phi2_s[(n + p) * MQ];
                #pragma unroll
                for (int ii = 0; ii < MQ; ++ii) {
                    ulonglong2 ph = prow[ii];
                    s2a[2 * ii]     = fma2(ph.x, x0_2, s2a[2 * ii]);
                    s2a[2 * ii + 1] = fma2(ph.y, x0_2, s2a[2 * ii + 1]);
                    s2b[2 * ii]     = fma2(ph.x, x1_2, s2b[2 * ii]);
                    s2b[2 * ii + 1] = fma2(ph.y, x1_2, s2b[2 * ii + 1]);
                }
            }
        }
    }

    // ---- fold r = y - s  (reuse s2 arrays as r2), one high-MLP LDG burst ----
    const unsigned long long neg1 = pack2(-1.0f, -1.0f);
    #pragma unroll
    for (int ii = 0; ii < MH; ++ii) {
        unsigned long long y2a = pack2(Y[(size_t)(2 * ii) * K + j0],
                                       Y[(size_t)(2 * ii + 1) * K + j0]);
        unsigned long long y2b = pack2(Y[(size_t)(2 * ii) * K + j1],
                                       Y[(size_t)(2 * ii + 1) * K + j1]);
        s2a[ii] = fma2(s2a[ii], neg1, y2a);
        s2b[ii] = fma2(s2b[ii], neg1, y2b);
    }

    // ---------------- Phase 2: u[n] = x[n] + s*<phi[:,n], r> ----------------
    {
        float xb0[4], xb1[4];
        #pragma unroll
        for (int p = 0; p < 4; ++p) {
            xb0[p] = X[(size_t)p * K + j0];
            xb1[p] = X[(size_t)p * K + j1];
        }

        #pragma unroll 1
        for (int n = 0; n < NROW; n += 4) {
            float xc0[4], xc1[4];
            #pragma unroll
            for (int p = 0; p < 4; ++p) { xc0[p] = xb0[p]; xc1[p] = xb1[p]; }
            #pragma unroll
            for (int p = 0; p < 4; ++p) {
                int np = n + 4 + p; np = (np < NROW) ? np : 0;
                xb0[p] = X[(size_t)np * K + j0];
                xb1[p] = X[(size_t)np * K + j1];
            }
            #pragma unroll
            for (int p = 0; p < 4; ++p) {
                const ulonglong2* prow = &phi2_s[(n + p) * MQ];
                unsigned long long a0 = 0ull, a1 = 0ull, b0 = 0ull, b1 = 0ull;
                #pragma unroll
                for (int ii = 0; ii < MQ; ++ii) {
                    ulonglong2 ph = prow[ii];
                    a0 = fma2(ph.x, s2a[2 * ii],     a0);
                    a1 = fma2(ph.y, s2a[2 * ii + 1], a1);
                    b0 = fma2(ph.x, s2b[2 * ii],     b0);
                    b1 = fma2(ph.y, s2b[2 * ii + 1], b1);
                }
                float alo, ahi, blo, bhi;
                unpack2(add2(a0, a1), alo, ahi);
                unpack2(add2(b0, b1), blo, bhi);
                float ua = fmaf(s, alo + ahi, xc0[p]);
                float ub = fmaf(s, blo + bhi, xc1[p]);
                ua = (fabsf(ua) > 0.1f) ? ua : 0.0f;
                ub = (fabsf(ub) > 0.1f) ? ub : 0.0f;
                outX[(size_t)(n + p) * K + j0] = act0 ? ua : xc0[p];
                if (j1 < K)
                    outX[(size_t)(n + p) * K + j1] = act1 ? ub : xc1[p];
            }
        }
    }
}

extern "C" void kernel_launch(void* const* d_in, const int* in_sizes, int n_in,
                              void* d_out, int out_size)
{
    const float* phi  = (const float*)d_in[0];
    const float* X    = (const float*)d_in[1];
    const float* Y    = (const float*)d_in[2];
    const float* step = (const float*)d_in[3];
    const int*   idx  = (const int*)d_in[4];

    const int phiN = in_sizes[0];
    const int XN   = in_sizes[1];
    const int K    = XN / NROW;

    float* outX = (float*)d_out;
    if (out_size == phiN + XN) {
        cudaMemcpyAsync(d_out, phi, (size_t)phiN * sizeof(float),
                        cudaMemcpyDeviceToDevice, 0);
        outX = (float*)d_out + phiN;
    }

    cudaFuncSetAttribute(ista_update_kernel,
                         cudaFuncAttributeMaxDynamicSharedMemorySize, SMEM_BYTES);

    const int grid = (K + CPB - 1) / CPB;
    ista_update_kernel<<<grid, TPB, SMEM_BYTES>>>(phi, X, Y, step, idx, outX, K);
}